// round 10
// baseline (speedup 1.0000x reference)
#include <cuda_runtime.h>
#include <cstdint>

// ---------------------------------------------------------------------------
// QuadTreeDecoder round 10
//  qt_l45_head: 2-column batch register blocking -> halves broadcast-LDS per
//  FFMA2 (kernel was smem-crossbar bound at L1=84.5%).
//  Packed f32x2 FMA everywhere. Activations act[node][i4][b] float4-interleaved.
// ---------------------------------------------------------------------------

typedef unsigned long long u64;

__device__ float4 g_x2[(size_t)16  * 16 * 128];
__device__ float4 g_x4[(size_t)256 * 16 * 128];
__device__ float  g_wf[(size_t)1024 * 4 * 48 * 16];

// ---------------------------------------------------------------------------
__device__ __forceinline__ void fma2(u64& d, u64 a, u64 b) {
    asm("fma.rn.f32x2 %0, %1, %2, %3;" : "=l"(d) : "l"(a), "l"(b), "l"(d));
}
__device__ __forceinline__ u64 pack2(float lo, float hi) {
    u64 r; asm("mov.b64 %0, {%1, %2};" : "=l"(r) : "f"(lo), "f"(hi)); return r;
}
__device__ __forceinline__ float fold2(u64 v) {
    float lo, hi; asm("mov.b64 {%0, %1}, %2;" : "=f"(lo), "=f"(hi) : "l"(v));
    return lo + hi;
}

// ---------------------------------------------------------------------------
__device__ __forceinline__ void stage_factor_n(float dst[16][64], const float* __restrict__ src,
                                               const float* __restrict__ sc, int tid, int nthr)
{
    const float4* s4 = (const float4*)src;
    float4* d4 = (float4*)dst;
    if (sc) {
        for (int idx = tid; idx < 256; idx += nthr) {
            float4 v = s4[idx];
            float s = __ldg(&sc[idx >> 4]);
            v.x *= s; v.y *= s; v.z *= s; v.w *= s;
            d4[idx] = v;
        }
    } else {
        for (int idx = tid; idx < 256; idx += nthr)
            d4[idx] = s4[idx];
    }
}

__device__ __forceinline__ void lat_from_smem(float lat[16],
        const float (*__restrict__ fi)[64], const float4 (*__restrict__ x_s)[64], int col)
{
    u64 acc[16];
#pragma unroll
    for (int r = 0; r < 16; r++) acc[r] = 0ull;
#pragma unroll 4
    for (int i4 = 0; i4 < 16; i4++) {
        ulonglong2 xv = *(const ulonglong2*)&x_s[i4][col];
#pragma unroll
        for (int r = 0; r < 16; r++) {
            ulonglong2 f = *(const ulonglong2*)&fi[r][i4 * 4];
            fma2(acc[r], xv.x, f.x);
            fma2(acc[r], xv.y, f.y);
        }
    }
#pragma unroll
    for (int r = 0; r < 16; r++) lat[r] = fold2(acc[r]);
}

__device__ __forceinline__ void duppack16(u64 lp[16], const float lat[16]) {
#pragma unroll
    for (int r = 0; r < 16; r++) lp[r] = pack2(lat[r], lat[r]);
}

__device__ __forceinline__ void update_smem(float4 (*x_s)[64],
        const float (*__restrict__ F)[64], const u64 lp[16], int col)
{
#pragma unroll 4
    for (int o4 = 0; o4 < 16; o4++) {
        ulonglong2 a = *(const ulonglong2*)&x_s[o4][col];
#pragma unroll
        for (int r = 0; r < 16; r++) {
            ulonglong2 f = *(const ulonglong2*)&F[r][o4 * 4];
            fma2(a.x, lp[r], f.x);
            fma2(a.y, lp[r], f.y);
        }
        *(ulonglong2*)&x_s[o4][col] = a;
    }
}

__device__ __forceinline__ void emit_global(float4* __restrict__ op,
        const float4 (*__restrict__ x_s)[64],
        const float (*__restrict__ F)[64], const u64 lp[16], int col)
{
#pragma unroll 4
    for (int o4 = 0; o4 < 16; o4++) {
        ulonglong2 a = *(const ulonglong2*)&x_s[o4][col];
#pragma unroll
        for (int r = 0; r < 16; r++) {
            ulonglong2 f = *(const ulonglong2*)&F[r][o4 * 4];
            fma2(a.x, lp[r], f.x);
            fma2(a.y, lp[r], f.y);
        }
        *(ulonglong2*)&op[o4 * 128] = a;
    }
}

// ---------------------------------------------------------------------------
// WF[p][c][k][r] = sum_o head_w[k][o] * F_c[341+p][r][o].  4096 blocks x 64.
// ---------------------------------------------------------------------------
__global__ __launch_bounds__(64)
void qt_wf_kernel(const float* __restrict__ ftl, const float* __restrict__ ftr,
                  const float* __restrict__ fbl, const float* __restrict__ fbr,
                  const float* __restrict__ head_w, float* __restrict__ wf)
{
    __shared__ __align__(16) float F_s[16][64];

    const int bid = blockIdx.x;
    const int p   = bid >> 2;
    const int c   = bid & 3;
    const int tid = threadIdx.x;
    const int node = 341 + p;

    const float* Fc = (c == 0 ? ftl : c == 1 ? ftr : c == 2 ? fbl : fbr)
                      + (size_t)node * 1024;
    stage_factor_n(F_s, Fc, nullptr, tid, 64);
    __syncthreads();

    if (tid < 48) {
        const int k = tid;
        const ulonglong2* wrow = (const ulonglong2*)(head_w + (size_t)k * 64);
        u64 acc[16];
#pragma unroll
        for (int r = 0; r < 16; r++) acc[r] = 0ull;
#pragma unroll 4
        for (int i4 = 0; i4 < 16; i4++) {
            ulonglong2 wv = wrow[i4];
#pragma unroll
            for (int r = 0; r < 16; r++) {
                ulonglong2 f = *(const ulonglong2*)&F_s[r][i4 * 4];
                fma2(acc[r], wv.x, f.x);
                fma2(acc[r], wv.y, f.y);
            }
        }
        float* dst = wf + ((size_t)p * 4 + c) * (48 * 16) + (size_t)k * 16;
#pragma unroll
        for (int r = 0; r < 16; r += 4)
            *(float4*)(dst + r) = make_float4(fold2(acc[r]), fold2(acc[r+1]),
                                              fold2(acc[r+2]), fold2(acc[r+3]));
    }
}

// ---------------------------------------------------------------------------
// Levels 0+1 fused. bid = (p1*4 + c1)*2 + qh. 32 blocks x 64.
// ---------------------------------------------------------------------------
__global__ __launch_bounds__(64)
void qt_l01(const float* __restrict__ x0, float4* __restrict__ xout,
            const float* __restrict__ fin,
            const float* __restrict__ ftl, const float* __restrict__ ftr,
            const float* __restrict__ fbl, const float* __restrict__ fbr,
            const float* __restrict__ scale)
{
    __shared__ __align__(16) float fiA[16][64], FA[16][64], fiB[16][64], FB[16][64];
    __shared__ float4 x_s[16][64];

    const int bid = blockIdx.x;
    const int p1  = bid >> 3;
    const int c1  = (bid >> 1) & 3;
    const int qh  = bid & 1;
    const int tid = threadIdx.x;

    const float* FcA = (p1 == 0 ? ftl : p1 == 1 ? ftr : p1 == 2 ? fbl : fbr);
    const int nodeB = 1 + p1;
    const float* FcB = (c1 == 0 ? ftl : c1 == 1 ? ftr : c1 == 2 ? fbl : fbr)
                       + (size_t)nodeB * 1024;

    stage_factor_n(fiA, fin, scale, tid, 64);
    stage_factor_n(FA,  FcA, nullptr, tid, 64);
    stage_factor_n(fiB, fin + (size_t)nodeB * 1024, scale + (size_t)nodeB * 16, tid, 64);
    stage_factor_n(FB,  FcB, nullptr, tid, 64);
    {
        const int b = qh * 64 + tid;
        const float4* xp = (const float4*)(x0 + (size_t)b * 64);
#pragma unroll
        for (int i4 = 0; i4 < 16; i4++)
            x_s[i4][tid] = xp[i4];
    }
    __syncthreads();

    float lat[16]; u64 lp[16];
    lat_from_smem(lat, fiA, x_s, tid);
    duppack16(lp, lat);
    update_smem(x_s, FA, lp, tid);
    lat_from_smem(lat, fiB, x_s, tid);
    duppack16(lp, lat);

    const int gr = p1 >> 1, gc = p1 & 1;
    const int cn = (2 * gr + (c1 >> 1)) * 4 + 2 * gc + (c1 & 1);
    float4* op = xout + ((size_t)cn * 16) * 128 + qh * 64 + tid;
    emit_global(op, x_s, FB, lp, tid);
}

// ---------------------------------------------------------------------------
// Levels 2+3 fused. bid = (p3*4 + c3)*2 + qh. 512 blocks x 64.
// ---------------------------------------------------------------------------
__global__ __launch_bounds__(64)
void qt_l23(const float4* __restrict__ xin, float4* __restrict__ xout,
            const float* __restrict__ fin,
            const float* __restrict__ ftl, const float* __restrict__ ftr,
            const float* __restrict__ fbl, const float* __restrict__ fbr,
            const float* __restrict__ scale)
{
    __shared__ __align__(16) float fiA[16][64], FA[16][64], fiB[16][64], FB[16][64];
    __shared__ float4 x_s[16][64];

    const int bid = blockIdx.x;
    const int p3  = bid >> 3;
    const int c3  = (bid >> 1) & 3;
    const int qh  = bid & 1;
    const int tid = threadIdx.x;

    const int r3 = p3 >> 3, k3 = p3 & 7;
    const int p2 = (r3 >> 1) * 4 + (k3 >> 1);
    const int c2 = ((r3 & 1) << 1) | (k3 & 1);

    const int nodeA = 5 + p2;
    const int nodeB = 21 + p3;
    const float* FcA = (c2 == 0 ? ftl : c2 == 1 ? ftr : c2 == 2 ? fbl : fbr)
                       + (size_t)nodeA * 1024;
    const float* FcB = (c3 == 0 ? ftl : c3 == 1 ? ftr : c3 == 2 ? fbl : fbr)
                       + (size_t)nodeB * 1024;

    stage_factor_n(fiA, fin + (size_t)nodeA * 1024, scale + (size_t)nodeA * 16, tid, 64);
    stage_factor_n(FA,  FcA, nullptr, tid, 64);
    stage_factor_n(fiB, fin + (size_t)nodeB * 1024, scale + (size_t)nodeB * 16, tid, 64);
    stage_factor_n(FB,  FcB, nullptr, tid, 64);
    {
        const float4* xp = xin + ((size_t)p2 * 16) * 128 + qh * 64 + tid;
#pragma unroll
        for (int i4 = 0; i4 < 16; i4++)
            x_s[i4][tid] = xp[i4 * 128];
    }
    __syncthreads();

    float lat[16]; u64 lp[16];
    lat_from_smem(lat, fiA, x_s, tid);
    duppack16(lp, lat);
    update_smem(x_s, FA, lp, tid);
    lat_from_smem(lat, fiB, x_s, tid);
    duppack16(lp, lat);

    const int gr = p3 >> 3, gc = p3 & 7;
    const int cn = (2 * gr + (c3 >> 1)) * 16 + 2 * gc + (c3 & 1);
    float4* op = xout + ((size_t)cn * 16) * 128 + qh * 64 + tid;
    emit_global(op, x_s, FB, lp, tid);
}

// ---------------------------------------------------------------------------
// Levels 4+5 + head, 2-col batch blocking.
// bid = p*2 + qh (2048 blocks), 128 threads = kq(4) x colg(32).
// Thread handles batch cols {colg, colg+32} of its half; owns 12 head k's.
// ---------------------------------------------------------------------------
__global__ __launch_bounds__(128, 3)
void qt_l45_head(const float4* __restrict__ xin,
                 const float* __restrict__ fin,
                 const float* __restrict__ ftl, const float* __restrict__ ftr,
                 const float* __restrict__ fbl, const float* __restrict__ fbr,
                 const float* __restrict__ scale,
                 const float* __restrict__ wf,
                 const float* __restrict__ head_w, const float* __restrict__ head_b,
                 float* __restrict__ out)
{
    // fac_s: fiA|FA|fiB during levels, re-used for wf afterwards.
    __shared__ __align__(16) float fac_s[3072];
    __shared__ __align__(16) float w_s[48][64];
    __shared__ __align__(16) float4 x_s[16][64];
    __shared__ float lat_s[16][64];
    __shared__ float hb_s[48];

    float (*fiA)[64] = (float (*)[64])(fac_s);
    float (*FA)[64]  = (float (*)[64])(fac_s + 1024);
    float (*fiB)[64] = (float (*)[64])(fac_s + 2048);

    const int bid  = blockIdx.x;
    const int p    = bid >> 1;          // level-5 node, grid-32 order
    const int qh   = bid & 1;           // batch half
    const int tid  = threadIdx.x;
    const int colg = tid & 31;
    const int kq   = tid >> 5;          // warp id == k-quarter

    const int r5 = p >> 5, c5 = p & 31;
    const int p4 = (r5 >> 1) * 16 + (c5 >> 1);
    const int c4 = ((r5 & 1) << 1) | (c5 & 1);
    const int nodeA = 85 + p4;
    const int nodeB = 341 + p;

    const float* FcA = (c4 == 0 ? ftl : c4 == 1 ? ftr : c4 == 2 ? fbl : fbr)
                       + (size_t)nodeA * 1024;

    stage_factor_n(fiA, fin + (size_t)nodeA * 1024, scale + (size_t)nodeA * 16, tid, 128);
    stage_factor_n(FA,  FcA, nullptr, tid, 128);
    stage_factor_n(fiB, fin + (size_t)nodeB * 1024, scale + (size_t)nodeB * 16, tid, 128);
    {
        const float4* w4 = (const float4*)head_w;
        float4* d4 = (float4*)w_s;
        for (int k = tid; k < 768; k += 128) d4[k] = w4[k];
        if (tid < 48) hb_s[tid] = head_b[tid];
        // x: 1024 float4, 8 per thread, coalesced
        const float4* xbase = xin + (size_t)p4 * 16 * 128 + qh * 64;
#pragma unroll
        for (int j = 0; j < 8; j++) {
            int idx = tid + j * 128;             // i4*64 + c
            x_s[idx >> 6][idx & 63] = xbase[(idx >> 6) * 128 + (idx & 63)];
        }
    }
    __syncthreads();

    const int rq = kq * 4;
    const int c0 = colg, c1 = colg + 32;

    // ---- P1: lat4 r-quarter for both cols -> lat_s
    {
        u64 a0[4], a1[4];
#pragma unroll
        for (int rr = 0; rr < 4; rr++) { a0[rr] = 0ull; a1[rr] = 0ull; }
#pragma unroll 4
        for (int i4 = 0; i4 < 16; i4++) {
            ulonglong2 xv0 = *(const ulonglong2*)&x_s[i4][c0];
            ulonglong2 xv1 = *(const ulonglong2*)&x_s[i4][c1];
#pragma unroll
            for (int rr = 0; rr < 4; rr++) {
                ulonglong2 f = *(const ulonglong2*)&fiA[rq + rr][i4 * 4];
                fma2(a0[rr], xv0.x, f.x); fma2(a0[rr], xv0.y, f.y);
                fma2(a1[rr], xv1.x, f.x); fma2(a1[rr], xv1.y, f.y);
            }
        }
#pragma unroll
        for (int rr = 0; rr < 4; rr++) {
            lat_s[rq + rr][c0] = fold2(a0[rr]);
            lat_s[rq + rr][c1] = fold2(a1[rr]);
        }
    }
    __syncthreads();

    // ---- P2: x update, o4-quarter, per-col serial (regs bounded)
#pragma unroll 1
    for (int j = 0; j < 2; j++) {
        const int col = colg + 32 * j;
        u64 lp[16];
#pragma unroll
        for (int r = 0; r < 16; r++) {
            float v = lat_s[r][col];
            lp[r] = pack2(v, v);
        }
#pragma unroll
        for (int oo = 0; oo < 4; oo++) {
            const int o4 = rq + oo;
            ulonglong2 a = *(const ulonglong2*)&x_s[o4][col];
#pragma unroll
            for (int r = 0; r < 16; r++) {
                ulonglong2 f = *(const ulonglong2*)&FA[r][o4 * 4];
                fma2(a.x, lp[r], f.x);
                fma2(a.y, lp[r], f.y);
            }
            *(ulonglong2*)&x_s[o4][col] = a;
        }
    }
    __syncthreads();

    // ---- P3: lat5 r-quarter for both cols -> lat_s
    {
        u64 a0[4], a1[4];
#pragma unroll
        for (int rr = 0; rr < 4; rr++) { a0[rr] = 0ull; a1[rr] = 0ull; }
#pragma unroll 4
        for (int i4 = 0; i4 < 16; i4++) {
            ulonglong2 xv0 = *(const ulonglong2*)&x_s[i4][c0];
            ulonglong2 xv1 = *(const ulonglong2*)&x_s[i4][c1];
#pragma unroll
            for (int rr = 0; rr < 4; rr++) {
                ulonglong2 f = *(const ulonglong2*)&fiB[rq + rr][i4 * 4];
                fma2(a0[rr], xv0.x, f.x); fma2(a0[rr], xv0.y, f.y);
                fma2(a1[rr], xv1.x, f.x); fma2(a1[rr], xv1.y, f.y);
            }
        }
#pragma unroll
        for (int rr = 0; rr < 4; rr++) {
            lat_s[rq + rr][c0] = fold2(a0[rr]);
            lat_s[rq + rr][c1] = fold2(a1[rr]);
        }
    }
    __syncthreads();

    // ---- P4: stage wf into fac_s (factors dead) + wx for both cols
    {
        const float4* wfp = (const float4*)(wf + (size_t)p * 3072);
        float4* wfs = (float4*)fac_s;
        for (int k = tid; k < 768; k += 128) wfs[k] = wfp[k];
    }

    const int k0 = kq * 12;
    float wx0[12], wx1[12];
    {
        u64 wxp0[12], wxp1[12];
#pragma unroll
        for (int kk = 0; kk < 12; kk++) { wxp0[kk] = 0ull; wxp1[kk] = 0ull; }
#pragma unroll 2
        for (int i4 = 0; i4 < 16; i4++) {
            ulonglong2 xv0 = *(const ulonglong2*)&x_s[i4][c0];
            ulonglong2 xv1 = *(const ulonglong2*)&x_s[i4][c1];
#pragma unroll
            for (int kk = 0; kk < 12; kk++) {
                ulonglong2 wv = *(const ulonglong2*)&w_s[k0 + kk][i4 * 4];
                fma2(wxp0[kk], xv0.x, wv.x); fma2(wxp0[kk], xv0.y, wv.y);
                fma2(wxp1[kk], xv1.x, wv.x); fma2(wxp1[kk], xv1.y, wv.y);
            }
        }
#pragma unroll
        for (int kk = 0; kk < 12; kk++) {
            float hb = hb_s[k0 + kk];
            wx0[kk] = fold2(wxp0[kk]) + hb;
            wx1[kk] = fold2(wxp1[kk]) + hb;
        }
    }

    // pack lat5 for both cols
    u64 latq0[8], latq1[8];
#pragma unroll
    for (int j4 = 0; j4 < 8; j4++) {
        latq0[j4] = pack2(lat_s[2*j4][c0], lat_s[2*j4 + 1][c0]);
        latq1[j4] = pack2(lat_s[2*j4][c1], lat_s[2*j4 + 1][c1]);
    }

    __syncthreads();   // wf_s (fac_s) ready

    const float (*wf_s)[16] = (const float (*)[16])fac_s;   // [c*48 + k][16]

    const int b0 = qh * 64 + c0;
    const int b1 = qh * 64 + c1;

#pragma unroll 1
    for (int c = 0; c < 4; c++) {
        const int cn = (2 * r5 + (c >> 1)) * 64 + 2 * c5 + (c & 1);

        float acc0[12], acc1[12];
#pragma unroll
        for (int kk = 0; kk < 12; kk++) {
            const ulonglong2* wfr = (const ulonglong2*)&wf_s[c * 48 + k0 + kk][0];
            u64 a0 = 0ull, a1 = 0ull;
#pragma unroll
            for (int j4 = 0; j4 < 4; j4++) {
                ulonglong2 f = wfr[j4];
                fma2(a0, latq0[2*j4],     f.x);
                fma2(a0, latq0[2*j4 + 1], f.y);
                fma2(a1, latq1[2*j4],     f.x);
                fma2(a1, latq1[2*j4 + 1], f.y);
            }
            acc0[kk] = wx0[kk] + fold2(a0);
            acc1[kk] = wx1[kk] + fold2(a1);
        }

        // k = kq*12 + pc*3 + oc  ->  pr == kq
        const int sr = cn >> 6, sc = cn & 63;
#pragma unroll
        for (int oc = 0; oc < 3; oc++) {
            float4 v0 = make_float4(acc0[0 + oc], acc0[3 + oc], acc0[6 + oc], acc0[9 + oc]);
            float4 v1 = make_float4(acc1[0 + oc], acc1[3 + oc], acc1[6 + oc], acc1[9 + oc]);
            size_t row0 = (size_t)(b0 * 3 + oc) * 256 + (sr * 4 + kq);
            size_t row1 = (size_t)(b1 * 3 + oc) * 256 + (sr * 4 + kq);
            *(float4*)(out + row0 * 256 + sc * 4) = v0;
            *(float4*)(out + row1 * 256 + sc * 4) = v1;
        }
    }
}

// ---------------------------------------------------------------------------
extern "C" void kernel_launch(void* const* d_in, const int* in_sizes, int n_in,
                              void* d_out, int out_size)
{
    const float* x      = (const float*)d_in[0];
    const float* fin    = (const float*)d_in[1];
    const float* ftl    = (const float*)d_in[2];
    const float* ftr    = (const float*)d_in[3];
    const float* fbl    = (const float*)d_in[4];
    const float* fbr    = (const float*)d_in[5];
    const float* scale  = (const float*)d_in[6];
    const float* head_w = (const float*)d_in[7];
    const float* head_b = (const float*)d_in[8];
    float* out = (float*)d_out;

    float4 *x2, *x4;
    float  *wfb;
    cudaGetSymbolAddress((void**)&x2,  g_x2);
    cudaGetSymbolAddress((void**)&x4,  g_x4);
    cudaGetSymbolAddress((void**)&wfb, g_wf);

    qt_wf_kernel<<<4096, 64>>>(ftl, ftr, fbl, fbr, head_w, wfb);
    qt_l01<<<32,  64>>>(x,  x2, fin, ftl, ftr, fbl, fbr, scale);
    qt_l23<<<512, 64>>>(x2, x4, fin, ftl, ftr, fbl, fbr, scale);
    qt_l45_head<<<2048, 128>>>(x4, fin, ftl, ftr, fbl, fbr, scale,
                               wfb, head_w, head_b, out);
}

// round 11
// speedup vs baseline: 1.0414x; 1.0414x over previous
#include <cuda_runtime.h>
#include <cstdint>

// ---------------------------------------------------------------------------
// QuadTreeDecoder round 11
//  Level-4-anchored algebra:
//    lat5 = fi5'.x4 + G.lat4,   G   = fi5'(scale-folded) . F4^T   (16x16)
//    y    = (W.x4+b) + WFA.lat4 + WF5_c.lat5,  WFA = W.F4^T (48x16)
//  -> wx computed once per level-4 node; x5 never materialized.
//  Packed f32x2 FMA everywhere. Activations act[node][i4][b] float4-interleaved.
// ---------------------------------------------------------------------------

typedef unsigned long long u64;

__device__ float4 g_x2[(size_t)16  * 16 * 128];
__device__ float4 g_x4[(size_t)256 * 16 * 128];
__device__ float  g_wf[(size_t)1024 * 4 * 48 * 16];   // WF5[cn][c][48][16]
__device__ float  g_wfa[(size_t)1024 * 48 * 16];      // WFA[cn][48][16]
__device__ float  g_g[(size_t)1024 * 16 * 16];        // G[cn][16][16]

// ---------------------------------------------------------------------------
__device__ __forceinline__ void fma2(u64& d, u64 a, u64 b) {
    asm("fma.rn.f32x2 %0, %1, %2, %3;" : "=l"(d) : "l"(a), "l"(b), "l"(d));
}
__device__ __forceinline__ u64 pack2(float lo, float hi) {
    u64 r; asm("mov.b64 %0, {%1, %2};" : "=l"(r) : "f"(lo), "f"(hi)); return r;
}
__device__ __forceinline__ float fold2(u64 v) {
    float lo, hi; asm("mov.b64 {%0, %1}, %2;" : "=f"(lo), "=f"(hi) : "l"(v));
    return lo + hi;
}

// ---------------------------------------------------------------------------
__device__ __forceinline__ void stage_factor_n(float dst[16][64], const float* __restrict__ src,
                                               const float* __restrict__ sc, int tid, int nthr)
{
    const float4* s4 = (const float4*)src;
    float4* d4 = (float4*)dst;
    if (sc) {
        for (int idx = tid; idx < 256; idx += nthr) {
            float4 v = s4[idx];
            float s = __ldg(&sc[idx >> 4]);
            v.x *= s; v.y *= s; v.z *= s; v.w *= s;
            d4[idx] = v;
        }
    } else {
        for (int idx = tid; idx < 256; idx += nthr)
            d4[idx] = s4[idx];
    }
}

__device__ __forceinline__ void lat_from_smem(float lat[16],
        const float (*__restrict__ fi)[64], const float4 (*__restrict__ x_s)[64], int col)
{
    u64 acc[16];
#pragma unroll
    for (int r = 0; r < 16; r++) acc[r] = 0ull;
#pragma unroll 4
    for (int i4 = 0; i4 < 16; i4++) {
        ulonglong2 xv = *(const ulonglong2*)&x_s[i4][col];
#pragma unroll
        for (int r = 0; r < 16; r++) {
            ulonglong2 f = *(const ulonglong2*)&fi[r][i4 * 4];
            fma2(acc[r], xv.x, f.x);
            fma2(acc[r], xv.y, f.y);
        }
    }
#pragma unroll
    for (int r = 0; r < 16; r++) lat[r] = fold2(acc[r]);
}

__device__ __forceinline__ void duppack16(u64 lp[16], const float lat[16]) {
#pragma unroll
    for (int r = 0; r < 16; r++) lp[r] = pack2(lat[r], lat[r]);
}

__device__ __forceinline__ void update_smem(float4 (*x_s)[64],
        const float (*__restrict__ F)[64], const u64 lp[16], int col)
{
#pragma unroll 4
    for (int o4 = 0; o4 < 16; o4++) {
        ulonglong2 a = *(const ulonglong2*)&x_s[o4][col];
#pragma unroll
        for (int r = 0; r < 16; r++) {
            ulonglong2 f = *(const ulonglong2*)&F[r][o4 * 4];
            fma2(a.x, lp[r], f.x);
            fma2(a.y, lp[r], f.y);
        }
        *(ulonglong2*)&x_s[o4][col] = a;
    }
}

__device__ __forceinline__ void emit_global(float4* __restrict__ op,
        const float4 (*__restrict__ x_s)[64],
        const float (*__restrict__ F)[64], const u64 lp[16], int col)
{
#pragma unroll 4
    for (int o4 = 0; o4 < 16; o4++) {
        ulonglong2 a = *(const ulonglong2*)&x_s[o4][col];
#pragma unroll
        for (int r = 0; r < 16; r++) {
            ulonglong2 f = *(const ulonglong2*)&F[r][o4 * 4];
            fma2(a.x, lp[r], f.x);
            fma2(a.y, lp[r], f.y);
        }
        *(ulonglong2*)&op[o4 * 128] = a;
    }
}

// ---------------------------------------------------------------------------
// WF5[cn][c][k][r] = sum_o head_w[k][o] * F_c[341+cn][r][o].  4096 blocks x 64.
// ---------------------------------------------------------------------------
__global__ __launch_bounds__(64)
void qt_wf_kernel(const float* __restrict__ ftl, const float* __restrict__ ftr,
                  const float* __restrict__ fbl, const float* __restrict__ fbr,
                  const float* __restrict__ head_w, float* __restrict__ wf)
{
    __shared__ __align__(16) float F_s[16][64];

    const int bid = blockIdx.x;
    const int p   = bid >> 2;
    const int c   = bid & 3;
    const int tid = threadIdx.x;
    const int node = 341 + p;

    const float* Fc = (c == 0 ? ftl : c == 1 ? ftr : c == 2 ? fbl : fbr)
                      + (size_t)node * 1024;
    stage_factor_n(F_s, Fc, nullptr, tid, 64);
    __syncthreads();

    if (tid < 48) {
        const int k = tid;
        const ulonglong2* wrow = (const ulonglong2*)(head_w + (size_t)k * 64);
        u64 acc[16];
#pragma unroll
        for (int r = 0; r < 16; r++) acc[r] = 0ull;
#pragma unroll 4
        for (int i4 = 0; i4 < 16; i4++) {
            ulonglong2 wv = __ldg(&wrow[i4]);
#pragma unroll
            for (int r = 0; r < 16; r++) {
                ulonglong2 f = *(const ulonglong2*)&F_s[r][i4 * 4];
                fma2(acc[r], wv.x, f.x);
                fma2(acc[r], wv.y, f.y);
            }
        }
        float* dst = wf + ((size_t)p * 4 + c) * (48 * 16) + (size_t)k * 16;
#pragma unroll
        for (int r = 0; r < 16; r += 4)
            *(float4*)(dst + r) = make_float4(fold2(acc[r]), fold2(acc[r+1]),
                                              fold2(acc[r+2]), fold2(acc[r+3]));
    }
}

// ---------------------------------------------------------------------------
// WFA[cn][k][r4] = sum_o W[k][o] * F4_{c4}[85+p4][r4][o]
// G  [cn][r][r4] = sum_o fi5s[341+cn][r][o] * F4_{c4}[85+p4][r4][o]
// 1024 blocks x 64 (threads 0..47: WFA rows; 48..63: G rows).
// ---------------------------------------------------------------------------
__global__ __launch_bounds__(64)
void qt_wfa_g_kernel(const float* __restrict__ ftl, const float* __restrict__ ftr,
                     const float* __restrict__ fbl, const float* __restrict__ fbr,
                     const float* __restrict__ fin, const float* __restrict__ scale,
                     const float* __restrict__ head_w,
                     float* __restrict__ wfa, float* __restrict__ gg)
{
    __shared__ __align__(16) float F_s[16][64];
    __shared__ __align__(16) float fi5s[16][64];

    const int cn  = blockIdx.x;
    const int tid = threadIdx.x;
    const int r5 = cn >> 5, c5 = cn & 31;
    const int p4 = (r5 >> 1) * 16 + (c5 >> 1);
    const int c4 = ((r5 & 1) << 1) | (c5 & 1);
    const int nodeA = 85 + p4;
    const int nodeB = 341 + cn;

    const float* Fc = (c4 == 0 ? ftl : c4 == 1 ? ftr : c4 == 2 ? fbl : fbr)
                      + (size_t)nodeA * 1024;
    stage_factor_n(F_s, Fc, nullptr, tid, 64);
    stage_factor_n(fi5s, fin + (size_t)nodeB * 1024, scale + (size_t)nodeB * 16, tid, 64);
    __syncthreads();

    if (tid < 48) {
        const int k = tid;
        const ulonglong2* wrow = (const ulonglong2*)(head_w + (size_t)k * 64);
        u64 acc[16];
#pragma unroll
        for (int r = 0; r < 16; r++) acc[r] = 0ull;
#pragma unroll 4
        for (int i4 = 0; i4 < 16; i4++) {
            ulonglong2 wv = __ldg(&wrow[i4]);
#pragma unroll
            for (int r = 0; r < 16; r++) {
                ulonglong2 f = *(const ulonglong2*)&F_s[r][i4 * 4];
                fma2(acc[r], wv.x, f.x);
                fma2(acc[r], wv.y, f.y);
            }
        }
        float* dst = wfa + (size_t)cn * 768 + (size_t)k * 16;
#pragma unroll
        for (int r = 0; r < 16; r += 4)
            *(float4*)(dst + r) = make_float4(fold2(acc[r]), fold2(acc[r+1]),
                                              fold2(acc[r+2]), fold2(acc[r+3]));
    } else {
        const int r = tid - 48;
        u64 acc[16];
#pragma unroll
        for (int r4 = 0; r4 < 16; r4++) acc[r4] = 0ull;
#pragma unroll 4
        for (int i4 = 0; i4 < 16; i4++) {
            ulonglong2 av = *(const ulonglong2*)&fi5s[r][i4 * 4];
#pragma unroll
            for (int r4 = 0; r4 < 16; r4++) {
                ulonglong2 f = *(const ulonglong2*)&F_s[r4][i4 * 4];
                fma2(acc[r4], av.x, f.x);
                fma2(acc[r4], av.y, f.y);
            }
        }
        float* dst = gg + (size_t)cn * 256 + (size_t)r * 16;
#pragma unroll
        for (int r4 = 0; r4 < 16; r4 += 4)
            *(float4*)(dst + r4) = make_float4(fold2(acc[r4]), fold2(acc[r4+1]),
                                               fold2(acc[r4+2]), fold2(acc[r4+3]));
    }
}

// ---------------------------------------------------------------------------
// Levels 0+1 fused. bid = (p1*4 + c1)*2 + qh. 32 blocks x 64.
// ---------------------------------------------------------------------------
__global__ __launch_bounds__(64)
void qt_l01(const float* __restrict__ x0, float4* __restrict__ xout,
            const float* __restrict__ fin,
            const float* __restrict__ ftl, const float* __restrict__ ftr,
            const float* __restrict__ fbl, const float* __restrict__ fbr,
            const float* __restrict__ scale)
{
    __shared__ __align__(16) float fiA[16][64], FA[16][64], fiB[16][64], FB[16][64];
    __shared__ float4 x_s[16][64];

    const int bid = blockIdx.x;
    const int p1  = bid >> 3;
    const int c1  = (bid >> 1) & 3;
    const int qh  = bid & 1;
    const int tid = threadIdx.x;

    const float* FcA = (p1 == 0 ? ftl : p1 == 1 ? ftr : p1 == 2 ? fbl : fbr);
    const int nodeB = 1 + p1;
    const float* FcB = (c1 == 0 ? ftl : c1 == 1 ? ftr : c1 == 2 ? fbl : fbr)
                       + (size_t)nodeB * 1024;

    stage_factor_n(fiA, fin, scale, tid, 64);
    stage_factor_n(FA,  FcA, nullptr, tid, 64);
    stage_factor_n(fiB, fin + (size_t)nodeB * 1024, scale + (size_t)nodeB * 16, tid, 64);
    stage_factor_n(FB,  FcB, nullptr, tid, 64);
    {
        const int b = qh * 64 + tid;
        const float4* xp = (const float4*)(x0 + (size_t)b * 64);
#pragma unroll
        for (int i4 = 0; i4 < 16; i4++)
            x_s[i4][tid] = xp[i4];
    }
    __syncthreads();

    float lat[16]; u64 lp[16];
    lat_from_smem(lat, fiA, x_s, tid);
    duppack16(lp, lat);
    update_smem(x_s, FA, lp, tid);
    lat_from_smem(lat, fiB, x_s, tid);
    duppack16(lp, lat);

    const int gr = p1 >> 1, gc = p1 & 1;
    const int cn = (2 * gr + (c1 >> 1)) * 4 + 2 * gc + (c1 & 1);
    float4* op = xout + ((size_t)cn * 16) * 128 + qh * 64 + tid;
    emit_global(op, x_s, FB, lp, tid);
}

// ---------------------------------------------------------------------------
// Levels 2+3 fused. bid = (p3*4 + c3)*2 + qh. 512 blocks x 64.
// ---------------------------------------------------------------------------
__global__ __launch_bounds__(64)
void qt_l23(const float4* __restrict__ xin, float4* __restrict__ xout,
            const float* __restrict__ fin,
            const float* __restrict__ ftl, const float* __restrict__ ftr,
            const float* __restrict__ fbl, const float* __restrict__ fbr,
            const float* __restrict__ scale)
{
    __shared__ __align__(16) float fiA[16][64], FA[16][64], fiB[16][64], FB[16][64];
    __shared__ float4 x_s[16][64];

    const int bid = blockIdx.x;
    const int p3  = bid >> 3;
    const int c3  = (bid >> 1) & 3;
    const int qh  = bid & 1;
    const int tid = threadIdx.x;

    const int r3 = p3 >> 3, k3 = p3 & 7;
    const int p2 = (r3 >> 1) * 4 + (k3 >> 1);
    const int c2 = ((r3 & 1) << 1) | (k3 & 1);

    const int nodeA = 5 + p2;
    const int nodeB = 21 + p3;
    const float* FcA = (c2 == 0 ? ftl : c2 == 1 ? ftr : c2 == 2 ? fbl : fbr)
                       + (size_t)nodeA * 1024;
    const float* FcB = (c3 == 0 ? ftl : c3 == 1 ? ftr : c3 == 2 ? fbl : fbr)
                       + (size_t)nodeB * 1024;

    stage_factor_n(fiA, fin + (size_t)nodeA * 1024, scale + (size_t)nodeA * 16, tid, 64);
    stage_factor_n(FA,  FcA, nullptr, tid, 64);
    stage_factor_n(fiB, fin + (size_t)nodeB * 1024, scale + (size_t)nodeB * 16, tid, 64);
    stage_factor_n(FB,  FcB, nullptr, tid, 64);
    {
        const float4* xp = xin + ((size_t)p2 * 16) * 128 + qh * 64 + tid;
#pragma unroll
        for (int i4 = 0; i4 < 16; i4++)
            x_s[i4][tid] = xp[i4 * 128];
    }
    __syncthreads();

    float lat[16]; u64 lp[16];
    lat_from_smem(lat, fiA, x_s, tid);
    duppack16(lp, lat);
    update_smem(x_s, FA, lp, tid);
    lat_from_smem(lat, fiB, x_s, tid);
    duppack16(lp, lat);

    const int gr = p3 >> 3, gc = p3 & 7;
    const int cn = (2 * gr + (c3 >> 1)) * 16 + 2 * gc + (c3 & 1);
    float4* op = xout + ((size_t)cn * 16) * 128 + qh * 64 + tid;
    emit_global(op, x_s, FB, lp, tid);
}

// ---------------------------------------------------------------------------
// Levels 4+5 + head, level-4 anchored.
// bid = p4*4 + q4 (1024 blocks), 128 threads = kq(4) x col(32).
//   P1+P2 (one x pass): lat4 (r-quarter, coop) + wx (own 12 k's, regs)
//   per level-5 child: lat5 = fiB'.x4 + G.lat4 ; tk = wx + WFA.lat4 ;
//                      per c: y = tk + WF5_c.lat5 -> pixels.
// ---------------------------------------------------------------------------
__global__ __launch_bounds__(128, 4)
void qt_l45_head(const float4* __restrict__ xin,
                 const float* __restrict__ fin,
                 const float* __restrict__ scale,
                 const float* __restrict__ wf,   // WF5
                 const float* __restrict__ wfa,  // WFA
                 const float* __restrict__ gg,   // G
                 const float* __restrict__ head_w, const float* __restrict__ head_b,
                 float* __restrict__ out)
{
    __shared__ __align__(16) float bufA[1024];   // fiA, then fiB per child
    __shared__ __align__(16) float bufW[3072];   // W (48x64), then WF5 (4x48x16)
    __shared__ __align__(16) float wfa_s[48][16];
    __shared__ __align__(16) float g_s[16][16];
    __shared__ __align__(16) float4 x_s[16][32];
    __shared__ float lat4_s[16][32];
    __shared__ float lat5_s[16][32];
    __shared__ float hb_s[48];

    float (*fiA)[64] = (float (*)[64])bufA;
    float (*w_s)[64] = (float (*)[64])bufW;

    const int bid  = blockIdx.x;
    const int p4   = bid >> 2;          // level-4 node, grid-16 order
    const int q4   = bid & 3;           // batch quarter
    const int tid  = threadIdx.x;
    const int col  = tid & 31;
    const int kq   = tid >> 5;
    const int rq   = kq * 4;
    const int k0   = kq * 12;

    const int gr4 = p4 >> 4, gc4 = p4 & 15;
    const int nodeA = 85 + p4;

    stage_factor_n(fiA, fin + (size_t)nodeA * 1024, scale + (size_t)nodeA * 16, tid, 128);
    {
        const float4* w4 = (const float4*)head_w;
        float4* d4 = (float4*)bufW;
        for (int k = tid; k < 768; k += 128) d4[k] = w4[k];
        if (tid < 48) hb_s[tid] = head_b[tid];
        const float4* xbase = xin + (size_t)p4 * 16 * 128 + q4 * 32;
#pragma unroll
        for (int j = 0; j < 4; j++) {
            int idx = tid + j * 128;             // i4*32 + c
            x_s[idx >> 5][idx & 31] = xbase[(idx >> 5) * 128 + (idx & 31)];
        }
    }
    __syncthreads();

    // ---- P1+P2 fused: one pass over x -> lat4 quarter + wx (own 12 k's)
    float wxv[12];
    {
        u64 a4[4];
        u64 wxp[12];
#pragma unroll
        for (int rr = 0; rr < 4; rr++) a4[rr] = 0ull;
#pragma unroll
        for (int kk = 0; kk < 12; kk++) wxp[kk] = 0ull;
#pragma unroll 2
        for (int i4 = 0; i4 < 16; i4++) {
            ulonglong2 xv = *(const ulonglong2*)&x_s[i4][col];
#pragma unroll
            for (int rr = 0; rr < 4; rr++) {
                ulonglong2 f = *(const ulonglong2*)&fiA[rq + rr][i4 * 4];
                fma2(a4[rr], xv.x, f.x);
                fma2(a4[rr], xv.y, f.y);
            }
#pragma unroll
            for (int kk = 0; kk < 12; kk++) {
                ulonglong2 wv = *(const ulonglong2*)&w_s[k0 + kk][i4 * 4];
                fma2(wxp[kk], xv.x, wv.x);
                fma2(wxp[kk], xv.y, wv.y);
            }
        }
#pragma unroll
        for (int rr = 0; rr < 4; rr++) lat4_s[rq + rr][col] = fold2(a4[rr]);
#pragma unroll
        for (int kk = 0; kk < 12; kk++) wxv[kk] = fold2(wxp[kk]) + hb_s[k0 + kk];
    }
    __syncthreads();

    // lat4 packed (own col)
    u64 latq4[8];
#pragma unroll
    for (int j = 0; j < 8; j++)
        latq4[j] = pack2(lat4_s[2*j][col], lat4_s[2*j + 1][col]);

    const int b = q4 * 32 + col;

    // ---- loop over 4 level-5 children of p4
#pragma unroll 1
    for (int j4 = 0; j4 < 4; j4++) {
        if (j4) __syncthreads();          // protect staging buffers
        const int cn = (2 * gr4 + (j4 >> 1)) * 32 + 2 * gc4 + (j4 & 1);
        const int nodeB = 341 + cn;

        // stage fiB (into bufA), WFA, G, WF5 (into bufW)
        stage_factor_n(fiA, fin + (size_t)nodeB * 1024, scale + (size_t)nodeB * 16, tid, 128);
        {
            const float4* s = (const float4*)(wfa + (size_t)cn * 768);
            float4* d = (float4*)wfa_s;
            for (int i = tid; i < 192; i += 128) d[i] = s[i];
            if (tid < 64)
                ((float4*)g_s)[tid] = ((const float4*)(gg + (size_t)cn * 256))[tid];
            const float4* s5 = (const float4*)(wf + (size_t)cn * 3072);
            float4* d5 = (float4*)bufW;
            for (int i = tid; i < 768; i += 128) d5[i] = s5[i];
        }
        __syncthreads();

        // ---- lat5 quarter: fiB'.x4 + G.lat4
        {
            u64 a5[4];
#pragma unroll
            for (int rr = 0; rr < 4; rr++) a5[rr] = 0ull;
#pragma unroll 2
            for (int i4 = 0; i4 < 16; i4++) {
                ulonglong2 xv = *(const ulonglong2*)&x_s[i4][col];
#pragma unroll
                for (int rr = 0; rr < 4; rr++) {
                    ulonglong2 f = *(const ulonglong2*)&fiA[rq + rr][i4 * 4];
                    fma2(a5[rr], xv.x, f.x);
                    fma2(a5[rr], xv.y, f.y);
                }
            }
#pragma unroll
            for (int rr = 0; rr < 4; rr++) {
                const ulonglong2* grow = (const ulonglong2*)&g_s[rq + rr][0];
#pragma unroll
                for (int j = 0; j < 4; j++) {
                    ulonglong2 f = grow[j];
                    fma2(a5[rr], latq4[2*j],     f.x);
                    fma2(a5[rr], latq4[2*j + 1], f.y);
                }
                lat5_s[rq + rr][col] = fold2(a5[rr]);
            }
        }
        __syncthreads();

        u64 latq5[8];
#pragma unroll
        for (int j = 0; j < 8; j++)
            latq5[j] = pack2(lat5_s[2*j][col], lat5_s[2*j + 1][col]);

        // ---- tk = wx + WFA.lat4 (own 12 k's)
        float tk[12];
#pragma unroll
        for (int kk = 0; kk < 12; kk++) {
            const ulonglong2* ar = (const ulonglong2*)&wfa_s[k0 + kk][0];
            u64 a = 0ull;
#pragma unroll
            for (int j = 0; j < 4; j++) {
                ulonglong2 f = ar[j];
                fma2(a, latq4[2*j],     f.x);
                fma2(a, latq4[2*j + 1], f.y);
            }
            tk[kk] = wxv[kk] + fold2(a);
        }

        // ---- 4 grandchildren: y = tk + WF5_c.lat5 -> pixels
        const float (*wf_s)[16] = (const float (*)[16])bufW;   // [c*48 + k][16]
        const int r5 = cn >> 5, c5 = cn & 31;

#pragma unroll 1
        for (int c = 0; c < 4; c++) {
            const int cn6 = (2 * r5 + (c >> 1)) * 64 + 2 * c5 + (c & 1);

            float acc[12];
#pragma unroll
            for (int kk = 0; kk < 12; kk++) {
                const ulonglong2* wfr = (const ulonglong2*)&wf_s[c * 48 + k0 + kk][0];
                u64 a = 0ull;
#pragma unroll
                for (int j = 0; j < 4; j++) {
                    ulonglong2 f = wfr[j];
                    fma2(a, latq5[2*j],     f.x);
                    fma2(a, latq5[2*j + 1], f.y);
                }
                acc[kk] = tk[kk] + fold2(a);
            }

            // k = kq*12 + pc*3 + oc -> pr == kq
            const int sr = cn6 >> 6, sc = cn6 & 63;
#pragma unroll
            for (int oc = 0; oc < 3; oc++) {
                float4 v = make_float4(acc[0 + oc], acc[3 + oc], acc[6 + oc], acc[9 + oc]);
                size_t row = (size_t)(b * 3 + oc) * 256 + (sr * 4 + kq);
                *(float4*)(out + row * 256 + sc * 4) = v;
            }
        }
    }
}

// ---------------------------------------------------------------------------
extern "C" void kernel_launch(void* const* d_in, const int* in_sizes, int n_in,
                              void* d_out, int out_size)
{
    const float* x      = (const float*)d_in[0];
    const float* fin    = (const float*)d_in[1];
    const float* ftl    = (const float*)d_in[2];
    const float* ftr    = (const float*)d_in[3];
    const float* fbl    = (const float*)d_in[4];
    const float* fbr    = (const float*)d_in[5];
    const float* scale  = (const float*)d_in[6];
    const float* head_w = (const float*)d_in[7];
    const float* head_b = (const float*)d_in[8];
    float* out = (float*)d_out;

    float4 *x2, *x4;
    float  *wfb, *wfab, *ggb;
    cudaGetSymbolAddress((void**)&x2,   g_x2);
    cudaGetSymbolAddress((void**)&x4,   g_x4);
    cudaGetSymbolAddress((void**)&wfb,  g_wf);
    cudaGetSymbolAddress((void**)&wfab, g_wfa);
    cudaGetSymbolAddress((void**)&ggb,  g_g);

    qt_wf_kernel<<<4096, 64>>>(ftl, ftr, fbl, fbr, head_w, wfb);
    qt_wfa_g_kernel<<<1024, 64>>>(ftl, ftr, fbl, fbr, fin, scale, head_w, wfab, ggb);
    qt_l01<<<32,  64>>>(x,  x2, fin, ftl, ftr, fbl, fbr, scale);
    qt_l23<<<512, 64>>>(x2, x4, fin, ftl, ftr, fbl, fbr, scale);
    qt_l45_head<<<1024, 128>>>(x4, fin, scale, wfb, wfab, ggb,
                               head_w, head_b, out);
}